// round 1
// baseline (speedup 1.0000x reference)
#include <cuda_runtime.h>
#include <math.h>

// Problem shape (fixed by the dataset): xyz1 (16,2048,3), xyz2 (16,2048,3)
#define BB 16
#define NN 2048
#define MM 2048

constexpr float EPSv = 1e-9f;

// -------- device scratch (static globals: allocation-free per the rules) ----
__device__ float g_sqrtd[(size_t)BB * NN * MM];   // 268 MB, sqrt(d2), iteration-invariant
__device__ float g_w[(size_t)BB * NN * MM];       // 268 MB, w' of current iteration
__device__ float g_remainL[BB * NN];
__device__ float g_remainR[BB * MM];
__device__ float g_sumr[BB * MM];                 // column sums of w'
__device__ float g_colcost[BB * MM];              // column sums of w'*sqrtd
__device__ float g_cons[BB * MM];
__device__ float g_rowS[BB * NN];                 // row sums s_i (0 => row's w' is all-zero)

__device__ __forceinline__ float ex2f(float x) {
    float y; asm("ex2.approx.ftz.f32 %0, %1;" : "=f"(y) : "f"(x)); return y;
}
__device__ __forceinline__ float sqrt_approx(float x) {
    float y; asm("sqrt.approx.ftz.f32 %0, %1;" : "=f"(y) : "f"(x)); return y;
}

// ---------------------------------------------------------------------------
__global__ void init_kernel(float* __restrict__ out, float initL, float initR) {
    int idx = blockIdx.x * blockDim.x + threadIdx.x;
    if (idx < BB * NN) { g_remainL[idx] = initL; g_rowS[idx] = 0.f; }
    if (idx < BB * MM) { g_remainR[idx] = initR; g_sumr[idx] = 0.f; g_colcost[idx] = 0.f; }
    if (idx < BB) out[idx] = 0.f;
}

// Precompute sqrt(d2) once. Block = 8 warps; warp w owns a 256-col slice,
// lane owns 8 consecutive cols -> float4 coalesced stores.
__global__ void __launch_bounds__(256) sqrtd_kernel(const float* __restrict__ xyz1,
                                                    const float* __restrict__ xyz2) {
    const int b = blockIdx.y;
    const int warp = threadIdx.x >> 5, lane = threadIdx.x & 31;
    const int cbase = warp * 256 + lane * 8;
    const int row0 = blockIdx.x * 8;

    float x2[8], y2[8], z2[8];
    const float* p2 = xyz2 + ((size_t)b * MM + cbase) * 3;
#pragma unroll
    for (int k = 0; k < 8; k++) { x2[k] = p2[3*k]; y2[k] = p2[3*k+1]; z2[k] = p2[3*k+2]; }

#pragma unroll
    for (int r = 0; r < 8; r++) {
        const int i = row0 + r;
        const float* p1 = xyz1 + ((size_t)b * NN + i) * 3;
        const float x1 = p1[0], y1 = p1[1], z1 = p1[2];
        float v[8];
#pragma unroll
        for (int k = 0; k < 8; k++) {
            float dx = x1 - x2[k], dy = y1 - y2[k], dz = z1 - z2[k];
            v[k] = sqrt_approx(dx*dx + dy*dy + dz*dz);
        }
        float* o = g_sqrtd + ((size_t)(b * NN + i)) * MM + cbase;
        *(float4*)(o)     = make_float4(v[0], v[1], v[2], v[3]);
        *(float4*)(o + 4) = make_float4(v[4], v[5], v[6], v[7]);
    }
}

// One iteration of the annealing loop (everything except cons/remainR):
//  per row: [phase0] rdec_i = sum_l w'_old * cons  (fused remainL update from prev iter)
//           [phase1] e = exp(level*d2)*remainR, row-sum s_i
//           [phase2] w' = e * remainL/(s+EPS); store w'; accumulate column sums
// Column sums (sumr, colcost) accumulate in registers (columns are uniquely
// owned within a block), flushed with one atomicAdd per column per block.
template <bool SKIP>
__global__ void __launch_bounds__(256) passA_kernel(float lvl2, int zerolvl, int first) {
    const int b = blockIdx.y;
    const int warp = threadIdx.x >> 5, lane = threadIdx.x & 31;
    const int cbase = warp * 256 + lane * 8;
    const int row0 = blockIdx.x * 8;

    __shared__ float sm_red[16];
    __shared__ float sm_scale;
    __shared__ int   sm_flag;
    __shared__ float sm_oldS[8];

    float rr[8], cc[8];
    {
        const float4* p = (const float4*)(g_remainR + b * MM + cbase);
        float4 a = p[0], c4 = p[1];
        rr[0]=a.x; rr[1]=a.y; rr[2]=a.z; rr[3]=a.w;
        rr[4]=c4.x; rr[5]=c4.y; rr[6]=c4.z; rr[7]=c4.w;
    }
    if (!first) {
        const float4* p = (const float4*)(g_cons + b * MM + cbase);
        float4 a = p[0], c4 = p[1];
        cc[0]=a.x; cc[1]=a.y; cc[2]=a.z; cc[3]=a.w;
        cc[4]=c4.x; cc[5]=c4.y; cc[6]=c4.z; cc[7]=c4.w;
    } else {
#pragma unroll
        for (int k = 0; k < 8; k++) cc[k] = 0.f;
    }
    if (threadIdx.x < 8)
        sm_oldS[threadIdx.x] = first ? 0.f : g_rowS[b * NN + row0 + threadIdx.x];
    __syncthreads();

    float colsum[8], colcost[8];
#pragma unroll
    for (int k = 0; k < 8; k++) { colsum[k] = 0.f; colcost[k] = 0.f; }

    const float thr = SKIP ? (-126.0f / lvl2) : 3.0e38f;   // d2 < thr <=> exp arg > -126

    for (int r = 0; r < 8; r++) {
        const int i = row0 + r;
        const size_t base = ((size_t)(b * NN + i)) * MM + cbase;

        // phase0: remainL decrement from previous iteration's w' and cons
        float rdp = 0.f;
        if (!first && sm_oldS[r] != 0.f) {
            float4 wa = *(const float4*)(g_w + base);
            float4 wb = *(const float4*)(g_w + base + 4);
            rdp = wa.x*cc[0] + wa.y*cc[1] + wa.z*cc[2] + wa.w*cc[3]
                + wb.x*cc[4] + wb.y*cc[5] + wb.z*cc[6] + wb.w*cc[7];
        }

        // phase1: e and row sum
        float4 sa = *(const float4*)(g_sqrtd + base);
        float4 sb = *(const float4*)(g_sqrtd + base + 4);
        float sq[8] = {sa.x, sa.y, sa.z, sa.w, sb.x, sb.y, sb.z, sb.w};

        float e[8];
        float srow = 0.f;
        if (zerolvl) {
#pragma unroll
            for (int k = 0; k < 8; k++) { e[k] = rr[k]; srow += e[k]; }
        } else {
            bool active = true;
            if (SKIP) {
                float mn = sq[0];
#pragma unroll
                for (int k = 1; k < 8; k++) mn = fminf(mn, sq[k]);
                active = __any_sync(0xffffffffu, mn * mn < thr);
            }
            if (active) {
#pragma unroll
                for (int k = 0; k < 8; k++) {
                    float d2 = sq[k] * sq[k];
                    e[k] = ex2f(lvl2 * d2) * rr[k];
                    srow += e[k];
                }
            } else {
#pragma unroll
                for (int k = 0; k < 8; k++) e[k] = 0.f;
            }
        }

        // combined warp reduction of (rdec_partial, srow_partial)
#pragma unroll
        for (int off = 16; off > 0; off >>= 1) {
            rdp  += __shfl_down_sync(0xffffffffu, rdp,  off);
            srow += __shfl_down_sync(0xffffffffu, srow, off);
        }
        if (lane == 0) { sm_red[warp * 2] = rdp; sm_red[warp * 2 + 1] = srow; }
        __syncthreads();
        if (threadIdx.x == 0) {
            float rdec = 0.f, s = 0.f;
#pragma unroll
            for (int w2 = 0; w2 < 8; w2++) { rdec += sm_red[w2*2]; s += sm_red[w2*2+1]; }
            const int li = b * NN + i;
            float rl = fmaxf(g_remainL[li] - rdec, 0.f);
            g_remainL[li] = rl;
            g_rowS[li] = s;
            sm_scale = rl / (s + EPSv);
            sm_flag = (s == 0.f);
        }
        __syncthreads();

        // phase2: scale, store w', accumulate column sums (skip all-zero rows)
        if (!sm_flag) {
            const float scale = sm_scale;
            float w8[8];
#pragma unroll
            for (int k = 0; k < 8; k++) {
                float wv = e[k] * scale;
                w8[k] = wv;
                colsum[k]  += wv;
                colcost[k] += wv * sq[k];
            }
            *(float4*)(g_w + base)     = make_float4(w8[0], w8[1], w8[2], w8[3]);
            *(float4*)(g_w + base + 4) = make_float4(w8[4], w8[5], w8[6], w8[7]);
        }
    }

#pragma unroll
    for (int k = 0; k < 8; k++) atomicAdd(&g_sumr[b * MM + cbase + k], colsum[k]);
#pragma unroll
    for (int k = 0; k < 8; k++) atomicAdd(&g_colcost[b * MM + cbase + k], colcost[k]);
}

// Column saturation + remainR update + cost accumulation; also zeroes the
// column accumulators for the next iteration. One block per batch.
__global__ void cons_kernel(float* __restrict__ out) {
    const int b = blockIdx.x;
    float local = 0.f;
    for (int l = threadIdx.x; l < MM; l += 256) {
        const int idx = b * MM + l;
        float sr  = g_sumr[idx];
        float rrv = g_remainR[idx];
        float c = fminf(rrv / (sr + EPSv), 1.0f);
        g_cons[idx] = c;
        g_remainR[idx] = fmaxf(rrv - sr * c, 0.f);
        local += c * g_colcost[idx];
        g_sumr[idx] = 0.f;
        g_colcost[idx] = 0.f;
    }
    __shared__ float red[256];
    red[threadIdx.x] = local;
    __syncthreads();
    for (int s = 128; s > 0; s >>= 1) {
        if (threadIdx.x < s) red[threadIdx.x] += red[threadIdx.x + s];
        __syncthreads();
    }
    if (threadIdx.x == 0) out[b] += red[0];
}

// ---------------------------------------------------------------------------
extern "C" void kernel_launch(void* const* d_in, const int* in_sizes, int n_in,
                              void* d_out, int out_size) {
    (void)in_sizes; (void)n_in; (void)out_size;
    const float* xyz1 = (const float*)d_in[0];
    const float* xyz2 = (const float*)d_in[1];
    float* out = (float*)d_out;

    const float mx = (float)(NN > MM ? NN : MM);
    init_kernel<<<(BB * MM + 255) / 256, 256>>>(out, mx / (float)NN, mx / (float)MM);
    sqrtd_kernel<<<dim3(NN / 8, BB), 256>>>(xyz1, xyz2);

    const float LOG2E = 1.4426950408889634f;
    int first = 1;
    for (int j = 7; j >= -2; --j) {
        float level = (j == -2) ? 0.f : -powf(4.f, (float)j);
        float lvl2 = level * LOG2E;
        int zerolvl = (level == 0.f) ? 1 : 0;
        dim3 grid(NN / 8, BB);
        if (level < -200.f)
            passA_kernel<true><<<grid, 256>>>(lvl2, zerolvl, first);
        else
            passA_kernel<false><<<grid, 256>>>(lvl2, zerolvl, first);
        cons_kernel<<<BB, 256>>>(out);
        first = 0;
    }
}